// round 2
// baseline (speedup 1.0000x reference)
#include <cuda_runtime.h>
#include <cstdint>

#define SEQ    2048
#define BATCH  2
#define DIMC   1024
#define NHEAD  16
#define HDIM   64
#define MROWS  (BATCH * SEQ)   // 4096

// Scratch (device globals: no allocation allowed)
__device__ float g_q[MROWS * DIMC];
__device__ float g_k[MROWS * DIMC];
__device__ float g_v[MROWS * DIMC];
__device__ float g_o[MROWS * DIMC];

__device__ __forceinline__ uint32_t tf32r(float x) {
    uint32_t u;
    asm("cvt.rna.tf32.f32 %0, %1;" : "=r"(u) : "f"(x));
    return u;
}

__device__ __forceinline__ void mma8(float c[4],
                                     uint32_t a0, uint32_t a1, uint32_t a2, uint32_t a3,
                                     uint32_t b0, uint32_t b1) {
    asm volatile(
        "mma.sync.aligned.m16n8k8.row.col.f32.tf32.tf32.f32 "
        "{%0,%1,%2,%3}, {%4,%5,%6,%7}, {%8,%9}, {%0,%1,%2,%3};"
        : "+f"(c[0]), "+f"(c[1]), "+f"(c[2]), "+f"(c[3])
        : "r"(a0), "r"(a1), "r"(a2), "r"(a3), "r"(b0), "r"(b1));
}

__device__ __forceinline__ void split_store(float4 v, float* ph, float* pl) {
    float hx = __uint_as_float(tf32r(v.x)); ph[0] = hx; pl[0] = __uint_as_float(tf32r(v.x - hx));
    float hy = __uint_as_float(tf32r(v.y)); ph[1] = hy; pl[1] = __uint_as_float(tf32r(v.y - hy));
    float hz = __uint_as_float(tf32r(v.z)); ph[2] = hz; pl[2] = __uint_as_float(tf32r(v.z - hz));
    float hw = __uint_as_float(tf32r(v.w)); ph[3] = hw; pl[3] = __uint_as_float(tf32r(v.w - hw));
}

// ============================================================================
// 3xTF32 GEMM: C[m][n] = sum_k A[m][k] * W[n][k] (+ bias[n])
// A: MROWS x DIMC row-major, W: DIMC x DIMC row-major, C: MROWS x DIMC
// Block 128x128, BK=16, 8 warps (2x4), warp tile 64x32.
// ============================================================================
__global__ __launch_bounds__(256, 2)
void gemm3x_kernel(const float* __restrict__ A, const float* __restrict__ W,
                   float* __restrict__ C, const float* __restrict__ bias) {
    __shared__ float Ah[128][20], Al[128][20], Bh[128][20], Bl[128][20];

    const int tid  = threadIdx.x;
    const int lane = tid & 31;
    const int warp = tid >> 5;
    const int wm   = warp >> 2;      // 0..1
    const int wn   = warp & 3;       // 0..3
    const int m0   = blockIdx.y * 128;
    const int n0   = blockIdx.x * 128;

    float acc[4][4][4];
#pragma unroll
    for (int i = 0; i < 4; i++)
#pragma unroll
        for (int j = 0; j < 4; j++)
#pragma unroll
            for (int k = 0; k < 4; k++) acc[i][j][k] = 0.f;

    const int sr = tid >> 2;         // 0..63 (staging row)
    const int sc = (tid & 3) * 4;    // 0,4,8,12 (staging col)

    for (int kt = 0; kt < DIMC; kt += 16) {
        float4 a0v = *(const float4*)&A[(size_t)(m0 + sr)      * DIMC + kt + sc];
        float4 a1v = *(const float4*)&A[(size_t)(m0 + sr + 64) * DIMC + kt + sc];
        float4 b0v = *(const float4*)&W[(size_t)(n0 + sr)      * DIMC + kt + sc];
        float4 b1v = *(const float4*)&W[(size_t)(n0 + sr + 64) * DIMC + kt + sc];
        __syncthreads();
        split_store(a0v, &Ah[sr][sc],      &Al[sr][sc]);
        split_store(a1v, &Ah[sr + 64][sc], &Al[sr + 64][sc]);
        split_store(b0v, &Bh[sr][sc],      &Bl[sr][sc]);
        split_store(b1v, &Bh[sr + 64][sc], &Bl[sr + 64][sc]);
        __syncthreads();

#pragma unroll
        for (int ks = 0; ks < 2; ks++) {
            const int kk = (lane & 3) + ks * 8;
            uint32_t ah[4][4], al[4][4];
#pragma unroll
            for (int mt = 0; mt < 4; mt++) {
                int r = wm * 64 + mt * 16 + (lane >> 2);
                ah[mt][0] = __float_as_uint(Ah[r][kk]);
                ah[mt][1] = __float_as_uint(Ah[r + 8][kk]);
                ah[mt][2] = __float_as_uint(Ah[r][kk + 4]);
                ah[mt][3] = __float_as_uint(Ah[r + 8][kk + 4]);
                al[mt][0] = __float_as_uint(Al[r][kk]);
                al[mt][1] = __float_as_uint(Al[r + 8][kk]);
                al[mt][2] = __float_as_uint(Al[r][kk + 4]);
                al[mt][3] = __float_as_uint(Al[r + 8][kk + 4]);
            }
#pragma unroll
            for (int nt = 0; nt < 4; nt++) {
                int nn = wn * 32 + nt * 8 + (lane >> 2);
                uint32_t bh0 = __float_as_uint(Bh[nn][kk]);
                uint32_t bh1 = __float_as_uint(Bh[nn][kk + 4]);
                uint32_t bl0 = __float_as_uint(Bl[nn][kk]);
                uint32_t bl1 = __float_as_uint(Bl[nn][kk + 4]);
#pragma unroll
                for (int mt = 0; mt < 4; mt++) {
                    mma8(acc[mt][nt], ah[mt][0], ah[mt][1], ah[mt][2], ah[mt][3], bh0, bh1);
                    mma8(acc[mt][nt], al[mt][0], al[mt][1], al[mt][2], al[mt][3], bh0, bh1);
                    mma8(acc[mt][nt], ah[mt][0], ah[mt][1], ah[mt][2], ah[mt][3], bl0, bl1);
                }
            }
        }
    }

#pragma unroll
    for (int mt = 0; mt < 4; mt++) {
#pragma unroll
        for (int nt = 0; nt < 4; nt++) {
            int r = m0 + wm * 64 + mt * 16 + (lane >> 2);
            int c = n0 + wn * 32 + nt * 8 + (lane & 3) * 2;
            float bb0 = bias ? bias[c]     : 0.f;
            float bb1 = bias ? bias[c + 1] : 0.f;
            float2 v0 = make_float2(acc[mt][nt][0] + bb0, acc[mt][nt][1] + bb1);
            float2 v1 = make_float2(acc[mt][nt][2] + bb0, acc[mt][nt][3] + bb1);
            *(float2*)&C[(size_t)r       * DIMC + c] = v0;
            *(float2*)&C[(size_t)(r + 8) * DIMC + c] = v1;
        }
    }
}

// ============================================================================
// Flash attention (tf32). One CTA = (b, h, 64 query rows). 4 warps x 16 rows.
// q/k/v/o layout: [B*SEQ][DIMC] with head columns h*64..h*64+63.
// ============================================================================
__global__ __launch_bounds__(128)
void attn_kernel(const float* __restrict__ Q, const float* __restrict__ K,
                 const float* __restrict__ V, float* __restrict__ O) {
    __shared__ float Ks[64][68];   // K tile; reused as P tile; also Q staging
    __shared__ float Vs[64][72];   // V tile

    const int tid  = threadIdx.x;
    const int lane = tid & 31;
    const int warp = tid >> 5;
    const int bh   = blockIdx.y;
    const int b    = bh >> 4;
    const int h    = bh & 15;
    const int q0   = blockIdx.x * 64;
    const size_t base = ((size_t)b * SEQ) * DIMC + (size_t)h * HDIM;

    const int sr = tid >> 4;         // 0..7
    const int sc = (tid & 15) * 4;   // 0..60

    // Stage Q (fp32) into Ks, then fill Q fragments (scale 0.125 folded, tf32)
#pragma unroll
    for (int r = sr; r < 64; r += 8)
        *(float4*)&Ks[r][sc] = *(const float4*)&Q[base + (size_t)(q0 + r) * DIMC + sc];
    __syncthreads();

    uint32_t qf[8][4];
    {
        const int qr = warp * 16 + (lane >> 2);
#pragma unroll
        for (int ks = 0; ks < 8; ks++) {
            int d = ks * 8 + (lane & 3);
            qf[ks][0] = tf32r(0.125f * Ks[qr][d]);
            qf[ks][1] = tf32r(0.125f * Ks[qr + 8][d]);
            qf[ks][2] = tf32r(0.125f * Ks[qr][d + 4]);
            qf[ks][3] = tf32r(0.125f * Ks[qr + 8][d + 4]);
        }
    }

    float o_acc[8][4];
#pragma unroll
    for (int i = 0; i < 8; i++)
#pragma unroll
        for (int j = 0; j < 4; j++) o_acc[i][j] = 0.f;
    float m_lo = -INFINITY, m_hi = -INFINITY;
    float l_lo = 0.f, l_hi = 0.f;

    for (int t = 0; t < SEQ / 64; t++) {
        const int k0 = t * 64;
        __syncthreads();   // prior iter's P/V consumers done (also protects Q->qf at t=0)
#pragma unroll
        for (int r = sr; r < 64; r += 8) {
            float4 kv = *(const float4*)&K[base + (size_t)(k0 + r) * DIMC + sc];
            float4 vv = *(const float4*)&V[base + (size_t)(k0 + r) * DIMC + sc];
            kv.x = __uint_as_float(tf32r(kv.x)); kv.y = __uint_as_float(tf32r(kv.y));
            kv.z = __uint_as_float(tf32r(kv.z)); kv.w = __uint_as_float(tf32r(kv.w));
            vv.x = __uint_as_float(tf32r(vv.x)); vv.y = __uint_as_float(tf32r(vv.y));
            vv.z = __uint_as_float(tf32r(vv.z)); vv.w = __uint_as_float(tf32r(vv.w));
            *(float4*)&Ks[r][sc] = kv;
            *(float4*)&Vs[r][sc] = vv;
        }
        __syncthreads();

        // S = (0.125*Q) @ K^T   (64x64 per CTA, 16x64 per warp)
        float s[8][4];
#pragma unroll
        for (int i = 0; i < 8; i++)
#pragma unroll
            for (int j = 0; j < 4; j++) s[i][j] = 0.f;
#pragma unroll
        for (int ks = 0; ks < 8; ks++) {
#pragma unroll
            for (int nt = 0; nt < 8; nt++) {
                int key = nt * 8 + (lane >> 2);
                int d   = ks * 8 + (lane & 3);
                uint32_t b0 = __float_as_uint(Ks[key][d]);
                uint32_t b1 = __float_as_uint(Ks[key][d + 4]);
                mma8(s[nt], qf[ks][0], qf[ks][1], qf[ks][2], qf[ks][3], b0, b1);
            }
        }
        __syncthreads();   // all warps done reading Ks before it becomes P

        // Online softmax (rows r_lo = lane>>2, r_hi = +8 within the warp's 16)
        float mx_lo = -INFINITY, mx_hi = -INFINITY;
#pragma unroll
        for (int nt = 0; nt < 8; nt++) {
            mx_lo = fmaxf(mx_lo, fmaxf(s[nt][0], s[nt][1]));
            mx_hi = fmaxf(mx_hi, fmaxf(s[nt][2], s[nt][3]));
        }
        mx_lo = fmaxf(mx_lo, __shfl_xor_sync(0xffffffffu, mx_lo, 1));
        mx_lo = fmaxf(mx_lo, __shfl_xor_sync(0xffffffffu, mx_lo, 2));
        mx_hi = fmaxf(mx_hi, __shfl_xor_sync(0xffffffffu, mx_hi, 1));
        mx_hi = fmaxf(mx_hi, __shfl_xor_sync(0xffffffffu, mx_hi, 2));

        float mn_lo = fmaxf(m_lo, mx_lo);
        float mn_hi = fmaxf(m_hi, mx_hi);
        float al_lo = __expf(m_lo - mn_lo);
        float al_hi = __expf(m_hi - mn_hi);
        m_lo = mn_lo; m_hi = mn_hi;

        float sum_lo = 0.f, sum_hi = 0.f;
#pragma unroll
        for (int nt = 0; nt < 8; nt++) {
            s[nt][0] = __expf(s[nt][0] - mn_lo); sum_lo += s[nt][0];
            s[nt][1] = __expf(s[nt][1] - mn_lo); sum_lo += s[nt][1];
            s[nt][2] = __expf(s[nt][2] - mn_hi); sum_hi += s[nt][2];
            s[nt][3] = __expf(s[nt][3] - mn_hi); sum_hi += s[nt][3];
        }
        sum_lo += __shfl_xor_sync(0xffffffffu, sum_lo, 1);
        sum_lo += __shfl_xor_sync(0xffffffffu, sum_lo, 2);
        sum_hi += __shfl_xor_sync(0xffffffffu, sum_hi, 1);
        sum_hi += __shfl_xor_sync(0xffffffffu, sum_hi, 2);
        l_lo = l_lo * al_lo + sum_lo;
        l_hi = l_hi * al_hi + sum_hi;

#pragma unroll
        for (int nt = 0; nt < 8; nt++) {
            o_acc[nt][0] *= al_lo; o_acc[nt][1] *= al_lo;
            o_acc[nt][2] *= al_hi; o_acc[nt][3] *= al_hi;
        }

        // Store P (tf32-rounded) into own 16 rows of Ks
        {
            const int pr = warp * 16 + (lane >> 2);
#pragma unroll
            for (int nt = 0; nt < 8; nt++) {
                int pc = nt * 8 + (lane & 3) * 2;
                float2 p0 = make_float2(__uint_as_float(tf32r(s[nt][0])),
                                        __uint_as_float(tf32r(s[nt][1])));
                float2 p1 = make_float2(__uint_as_float(tf32r(s[nt][2])),
                                        __uint_as_float(tf32r(s[nt][3])));
                *(float2*)&Ks[pr][pc]     = p0;
                *(float2*)&Ks[pr + 8][pc] = p1;
            }
        }
        __syncwarp();

        // O += P @ V
        const int pr = warp * 16 + (lane >> 2);
#pragma unroll
        for (int ks = 0; ks < 8; ks++) {
            int pk = ks * 8 + (lane & 3);
            uint32_t a0 = __float_as_uint(Ks[pr][pk]);
            uint32_t a1 = __float_as_uint(Ks[pr + 8][pk]);
            uint32_t a2 = __float_as_uint(Ks[pr][pk + 4]);
            uint32_t a3 = __float_as_uint(Ks[pr + 8][pk + 4]);
#pragma unroll
            for (int nt = 0; nt < 8; nt++) {
                int d  = nt * 8 + (lane >> 2);
                int kr = ks * 8 + (lane & 3);
                uint32_t b0 = __float_as_uint(Vs[kr][d]);
                uint32_t b1 = __float_as_uint(Vs[kr + 4][d]);
                mma8(o_acc[nt], a0, a1, a2, a3, b0, b1);
            }
        }
    }

    // Epilogue: divide by l, write O
    float il_lo = 1.f / l_lo;
    float il_hi = 1.f / l_hi;
    const int orow = q0 + warp * 16 + (lane >> 2);
#pragma unroll
    for (int nt = 0; nt < 8; nt++) {
        int d = nt * 8 + (lane & 3) * 2;
        float2 v0 = make_float2(o_acc[nt][0] * il_lo, o_acc[nt][1] * il_lo);
        float2 v1 = make_float2(o_acc[nt][2] * il_hi, o_acc[nt][3] * il_hi);
        *(float2*)&O[base + (size_t)orow       * DIMC + d] = v0;
        *(float2*)&O[base + (size_t)(orow + 8) * DIMC + d] = v1;
    }
}

extern "C" void kernel_launch(void* const* d_in, const int* in_sizes, int n_in,
                              void* d_out, int out_size) {
    (void)in_sizes; (void)n_in; (void)out_size;
    const float* x  = (const float*)d_in[0];
    const float* Wq = (const float*)d_in[1];
    const float* Wk = (const float*)d_in[2];
    const float* Wv = (const float*)d_in[3];
    const float* Wp = (const float*)d_in[4];
    const float* bp = (const float*)d_in[5];
    float* out = (float*)d_out;

    float *qp, *kp, *vp, *op;
    cudaGetSymbolAddress((void**)&qp, g_q);
    cudaGetSymbolAddress((void**)&kp, g_k);
    cudaGetSymbolAddress((void**)&vp, g_v);
    cudaGetSymbolAddress((void**)&op, g_o);

    dim3 ggrid(DIMC / 128, MROWS / 128);   // (8, 32)
    gemm3x_kernel<<<ggrid, 256>>>(x, Wq, qp, nullptr);
    gemm3x_kernel<<<ggrid, 256>>>(x, Wk, kp, nullptr);
    gemm3x_kernel<<<ggrid, 256>>>(x, Wv, vp, nullptr);
    attn_kernel<<<dim3(SEQ / 64, BATCH * NHEAD), 128>>>(qp, kp, vp, op);
    gemm3x_kernel<<<ggrid, 256>>>(op, Wp, out, bp);
}

// round 5
// speedup vs baseline: 1.1181x; 1.1181x over previous
#include <cuda_runtime.h>
#include <cstdint>

#define SEQ    2048
#define BATCH  2
#define DIMC   1024
#define NHEAD  16
#define HDIM   64
#define MROWS  (BATCH * SEQ)   // 4096

// Scratch (device globals: no allocation allowed)
__device__ float g_q[MROWS * DIMC];
__device__ float g_k[MROWS * DIMC];
__device__ float g_v[MROWS * DIMC];
__device__ float g_o[MROWS * DIMC];

__device__ __forceinline__ uint32_t tf32r(float x) {
    uint32_t u;
    asm("cvt.rna.tf32.f32 %0, %1;" : "=r"(u) : "f"(x));
    return u;
}

__device__ __forceinline__ void mma8(float c[4],
                                     uint32_t a0, uint32_t a1, uint32_t a2, uint32_t a3,
                                     uint32_t b0, uint32_t b1) {
    asm volatile(
        "mma.sync.aligned.m16n8k8.row.col.f32.tf32.tf32.f32 "
        "{%0,%1,%2,%3}, {%4,%5,%6,%7}, {%8,%9}, {%0,%1,%2,%3};"
        : "+f"(c[0]), "+f"(c[1]), "+f"(c[2]), "+f"(c[3])
        : "r"(a0), "r"(a1), "r"(a2), "r"(a3), "r"(b0), "r"(b1));
}

__device__ __forceinline__ void cp_async16(uint32_t saddr, const void* gaddr) {
    asm volatile("cp.async.ca.shared.global [%0], [%1], 16;" :: "r"(saddr), "l"(gaddr));
}

// ============================================================================
// 3xTF32 GEMM, cp.async double-buffered, split-at-consume.
// C[m][n] = sum_k A[m][k] * W[n][k] (+ bias[n])
// Block 128x128, BK=16, 8 warps (2x4), warp tile 64x32.
// smem: raw fp32 tiles, 2 stages, 40KB total (static).
// ============================================================================
__global__ __launch_bounds__(256, 2)
void gemm3x_kernel(const float* __restrict__ A, const float* __restrict__ W,
                   float* __restrict__ C, const float* __restrict__ bias) {
    __shared__ float As[2][128][20];
    __shared__ float Bs[2][128][20];

    const int tid  = threadIdx.x;
    const int lane = tid & 31;
    const int warp = tid >> 5;
    const int wm   = warp >> 2;      // 0..1
    const int wn   = warp & 3;       // 0..3
    const int m0   = blockIdx.y * 128;
    const int n0   = blockIdx.x * 128;

    float acc[4][4][4];
#pragma unroll
    for (int i = 0; i < 4; i++)
#pragma unroll
        for (int j = 0; j < 4; j++)
#pragma unroll
            for (int k = 0; k < 4; k++) acc[i][j][k] = 0.f;

    const int sr = tid >> 2;         // 0..63
    const int sc = (tid & 3) * 4;    // 0,4,8,12

    const float* ga0 = A + (size_t)(m0 + sr)      * DIMC + sc;
    const float* ga1 = A + (size_t)(m0 + sr + 64) * DIMC + sc;
    const float* gb0 = W + (size_t)(n0 + sr)      * DIMC + sc;
    const float* gb1 = W + (size_t)(n0 + sr + 64) * DIMC + sc;

    const uint32_t stageB = 128 * 20 * 4;  // bytes per stage
    uint32_t sa0 = (uint32_t)__cvta_generic_to_shared(&As[0][sr][sc]);
    uint32_t sa1 = (uint32_t)__cvta_generic_to_shared(&As[0][sr + 64][sc]);
    uint32_t sb0 = (uint32_t)__cvta_generic_to_shared(&Bs[0][sr][sc]);
    uint32_t sb1 = (uint32_t)__cvta_generic_to_shared(&Bs[0][sr + 64][sc]);

    // Prologue: stage 0
    cp_async16(sa0, ga0); cp_async16(sa1, ga1);
    cp_async16(sb0, gb0); cp_async16(sb1, gb1);
    asm volatile("cp.async.commit_group;");

    for (int kt = 0; kt < DIMC / 16; kt++) {
        const int buf = kt & 1;
        if (kt + 1 < DIMC / 16) {
            const uint32_t off = (uint32_t)(buf ^ 1) * stageB;
            const int go = (kt + 1) * 16;
            cp_async16(sa0 + off, ga0 + go);
            cp_async16(sa1 + off, ga1 + go);
            cp_async16(sb0 + off, gb0 + go);
            cp_async16(sb1 + off, gb1 + go);
            asm volatile("cp.async.commit_group;");
            asm volatile("cp.async.wait_group 1;");
        } else {
            asm volatile("cp.async.wait_group 0;");
        }
        __syncthreads();

        const float (*Ab)[20] = As[buf];
        const float (*Bb)[20] = Bs[buf];

#pragma unroll
        for (int ks = 0; ks < 2; ks++) {
            const int kk = (lane & 3) + ks * 8;
            uint32_t ah[4][4], al[4][4];
#pragma unroll
            for (int mt = 0; mt < 4; mt++) {
                int r = wm * 64 + mt * 16 + (lane >> 2);
                float r0 = Ab[r][kk],     r1 = Ab[r + 8][kk];
                float r2 = Ab[r][kk + 4], r3 = Ab[r + 8][kk + 4];
                ah[mt][0] = tf32r(r0); al[mt][0] = tf32r(r0 - __uint_as_float(ah[mt][0]));
                ah[mt][1] = tf32r(r1); al[mt][1] = tf32r(r1 - __uint_as_float(ah[mt][1]));
                ah[mt][2] = tf32r(r2); al[mt][2] = tf32r(r2 - __uint_as_float(ah[mt][2]));
                ah[mt][3] = tf32r(r3); al[mt][3] = tf32r(r3 - __uint_as_float(ah[mt][3]));
            }
#pragma unroll
            for (int nt = 0; nt < 4; nt++) {
                int nn = wn * 32 + nt * 8 + (lane >> 2);
                float w0 = Bb[nn][kk], w1 = Bb[nn][kk + 4];
                uint32_t bh0 = tf32r(w0), bl0 = tf32r(w0 - __uint_as_float(bh0));
                uint32_t bh1 = tf32r(w1), bl1 = tf32r(w1 - __uint_as_float(bh1));
#pragma unroll
                for (int mt = 0; mt < 4; mt++) {
                    mma8(acc[mt][nt], ah[mt][0], ah[mt][1], ah[mt][2], ah[mt][3], bh0, bh1);
                    mma8(acc[mt][nt], al[mt][0], al[mt][1], al[mt][2], al[mt][3], bh0, bh1);
                    mma8(acc[mt][nt], ah[mt][0], ah[mt][1], ah[mt][2], ah[mt][3], bl0, bl1);
                }
            }
        }
        __syncthreads();
    }

#pragma unroll
    for (int mt = 0; mt < 4; mt++) {
#pragma unroll
        for (int nt = 0; nt < 4; nt++) {
            int r = m0 + wm * 64 + mt * 16 + (lane >> 2);
            int c = n0 + wn * 32 + nt * 8 + (lane & 3) * 2;
            float bb0 = bias ? bias[c]     : 0.f;
            float bb1 = bias ? bias[c + 1] : 0.f;
            float2 v0 = make_float2(acc[mt][nt][0] + bb0, acc[mt][nt][1] + bb1);
            float2 v1 = make_float2(acc[mt][nt][2] + bb0, acc[mt][nt][3] + bb1);
            *(float2*)&C[(size_t)r       * DIMC + c] = v0;
            *(float2*)&C[(size_t)(r + 8) * DIMC + c] = v1;
        }
    }
}

// ============================================================================
// Flash attention (tf32), 2 Q-strips per warp for B-operand reuse.
// CTA = (b, h, 128 q rows). 4 warps x 32 rows (2 strips of 16).
// Dynamic smem: Ks[64][68] + Vs[64][72] + Ps[128][68] = 70656 B.
// ============================================================================
#define ATTN_SMEM ((64 * 68 + 64 * 72 + 128 * 68) * 4)

__global__ __launch_bounds__(128)
void attn_kernel(const float* __restrict__ Q, const float* __restrict__ K,
                 const float* __restrict__ V, float* __restrict__ O) {
    extern __shared__ float sm[];
    float (*Ks)[68] = (float(*)[68])sm;                       // 64 rows (K tile)
    float (*Vs)[72] = (float(*)[72])(sm + 64 * 68);           // 64 rows (V tile)
    float (*Ps)[68] = (float(*)[68])(sm + 64 * 68 + 64 * 72); // 128 rows (P)

    const int tid  = threadIdx.x;
    const int lane = tid & 31;
    const int warp = tid >> 5;
    const int bh   = blockIdx.y;
    const int b    = bh >> 4;
    const int h    = bh & 15;
    const int q0   = blockIdx.x * 128;
    const size_t base = ((size_t)b * SEQ) * DIMC + (size_t)h * HDIM;

    // Q fragments for both strips, direct from gmem (once), scale folded.
    uint32_t qf[2][8][4];
#pragma unroll
    for (int s = 0; s < 2; s++) {
        int qr = q0 + warp * 32 + s * 16 + (lane >> 2);
        const float* qp0 = Q + base + (size_t)qr * DIMC;
        const float* qp1 = qp0 + (size_t)8 * DIMC;
#pragma unroll
        for (int ks = 0; ks < 8; ks++) {
            int d = ks * 8 + (lane & 3);
            qf[s][ks][0] = tf32r(0.125f * qp0[d]);
            qf[s][ks][1] = tf32r(0.125f * qp1[d]);
            qf[s][ks][2] = tf32r(0.125f * qp0[d + 4]);
            qf[s][ks][3] = tf32r(0.125f * qp1[d + 4]);
        }
    }

    float o0[8][4], o1[8][4];
#pragma unroll
    for (int i = 0; i < 8; i++)
#pragma unroll
        for (int j = 0; j < 4; j++) { o0[i][j] = 0.f; o1[i][j] = 0.f; }
    // m/l state: [strip][lo/hi rows]
    float m_s0l = -INFINITY, m_s0h = -INFINITY, m_s1l = -INFINITY, m_s1h = -INFINITY;
    float l_s0l = 0.f, l_s0h = 0.f, l_s1l = 0.f, l_s1h = 0.f;

    const int sr = tid >> 4;         // 0..7
    const int sc = (tid & 15) * 4;   // 0..60

    for (int t = 0; t < SEQ / 64; t++) {
        const int k0 = t * 64;
        __syncthreads();
#pragma unroll
        for (int r = sr; r < 64; r += 8) {
            float4 kv = *(const float4*)&K[base + (size_t)(k0 + r) * DIMC + sc];
            float4 vv = *(const float4*)&V[base + (size_t)(k0 + r) * DIMC + sc];
            kv.x = __uint_as_float(tf32r(kv.x)); kv.y = __uint_as_float(tf32r(kv.y));
            kv.z = __uint_as_float(tf32r(kv.z)); kv.w = __uint_as_float(tf32r(kv.w));
            vv.x = __uint_as_float(tf32r(vv.x)); vv.y = __uint_as_float(tf32r(vv.y));
            vv.z = __uint_as_float(tf32r(vv.z)); vv.w = __uint_as_float(tf32r(vv.w));
            *(float4*)&Ks[r][sc] = kv;
            *(float4*)&Vs[r][sc] = vv;
        }
        __syncthreads();

        // S = (0.125*Q) @ K^T for BOTH strips — each K fragment feeds 2 MMAs.
        float s0[8][4], s1[8][4];
#pragma unroll
        for (int i = 0; i < 8; i++)
#pragma unroll
            for (int j = 0; j < 4; j++) { s0[i][j] = 0.f; s1[i][j] = 0.f; }
#pragma unroll
        for (int ks = 0; ks < 8; ks++) {
            const int d = ks * 8 + (lane & 3);
#pragma unroll
            for (int nt = 0; nt < 8; nt++) {
                int key = nt * 8 + (lane >> 2);
                uint32_t b0 = __float_as_uint(Ks[key][d]);
                uint32_t b1 = __float_as_uint(Ks[key][d + 4]);
                mma8(s0[nt], qf[0][ks][0], qf[0][ks][1], qf[0][ks][2], qf[0][ks][3], b0, b1);
                mma8(s1[nt], qf[1][ks][0], qf[1][ks][1], qf[1][ks][2], qf[1][ks][3], b0, b1);
            }
        }

        // Online softmax per strip; write P (tf32) into warp's Ps rows.
        auto softmax_strip = [&](float s[8][4], float& m_lo, float& m_hi,
                                 float& l_lo, float& l_hi, float o[8][4], int prow) {
            float mx_lo = -INFINITY, mx_hi = -INFINITY;
#pragma unroll
            for (int nt = 0; nt < 8; nt++) {
                mx_lo = fmaxf(mx_lo, fmaxf(s[nt][0], s[nt][1]));
                mx_hi = fmaxf(mx_hi, fmaxf(s[nt][2], s[nt][3]));
            }
            mx_lo = fmaxf(mx_lo, __shfl_xor_sync(0xffffffffu, mx_lo, 1));
            mx_lo = fmaxf(mx_lo, __shfl_xor_sync(0xffffffffu, mx_lo, 2));
            mx_hi = fmaxf(mx_hi, __shfl_xor_sync(0xffffffffu, mx_hi, 1));
            mx_hi = fmaxf(mx_hi, __shfl_xor_sync(0xffffffffu, mx_hi, 2));

            float mn_lo = fmaxf(m_lo, mx_lo);
            float mn_hi = fmaxf(m_hi, mx_hi);
            float al_lo = __expf(m_lo - mn_lo);
            float al_hi = __expf(m_hi - mn_hi);
            m_lo = mn_lo; m_hi = mn_hi;

            float sum_lo = 0.f, sum_hi = 0.f;
#pragma unroll
            for (int nt = 0; nt < 8; nt++) {
                s[nt][0] = __expf(s[nt][0] - mn_lo); sum_lo += s[nt][0];
                s[nt][1] = __expf(s[nt][1] - mn_lo); sum_lo += s[nt][1];
                s[nt][2] = __expf(s[nt][2] - mn_hi); sum_hi += s[nt][2];
                s[nt][3] = __expf(s[nt][3] - mn_hi); sum_hi += s[nt][3];
            }
            sum_lo += __shfl_xor_sync(0xffffffffu, sum_lo, 1);
            sum_lo += __shfl_xor_sync(0xffffffffu, sum_lo, 2);
            sum_hi += __shfl_xor_sync(0xffffffffu, sum_hi, 1);
            sum_hi += __shfl_xor_sync(0xffffffffu, sum_hi, 2);
            l_lo = l_lo * al_lo + sum_lo;
            l_hi = l_hi * al_hi + sum_hi;

#pragma unroll
            for (int nt = 0; nt < 8; nt++) {
                o[nt][0] *= al_lo; o[nt][1] *= al_lo;
                o[nt][2] *= al_hi; o[nt][3] *= al_hi;
            }
            const int pr = prow + (lane >> 2);
#pragma unroll
            for (int nt = 0; nt < 8; nt++) {
                int pc = nt * 8 + (lane & 3) * 2;
                float2 p0 = make_float2(__uint_as_float(tf32r(s[nt][0])),
                                        __uint_as_float(tf32r(s[nt][1])));
                float2 p1 = make_float2(__uint_as_float(tf32r(s[nt][2])),
                                        __uint_as_float(tf32r(s[nt][3])));
                *(float2*)&Ps[pr][pc]     = p0;
                *(float2*)&Ps[pr + 8][pc] = p1;
            }
        };

        softmax_strip(s0, m_s0l, m_s0h, l_s0l, l_s0h, o0, warp * 32);
        softmax_strip(s1, m_s1l, m_s1h, l_s1l, l_s1h, o1, warp * 32 + 16);
        __syncwarp();   // Ps writer == reader warp

        // O += P @ V — each V fragment feeds 2 MMAs (both strips).
        const int prA = warp * 32 + (lane >> 2);
#pragma unroll
        for (int ks = 0; ks < 8; ks++) {
            const int pk = ks * 8 + (lane & 3);
            uint32_t aA0 = __float_as_uint(Ps[prA][pk]);
            uint32_t aA1 = __float_as_uint(Ps[prA + 8][pk]);
            uint32_t aA2 = __float_as_uint(Ps[prA][pk + 4]);
            uint32_t aA3 = __float_as_uint(Ps[prA + 8][pk + 4]);
            uint32_t aB0 = __float_as_uint(Ps[prA + 16][pk]);
            uint32_t aB1 = __float_as_uint(Ps[prA + 24][pk]);
            uint32_t aB2 = __float_as_uint(Ps[prA + 16][pk + 4]);
            uint32_t aB3 = __float_as_uint(Ps[prA + 24][pk + 4]);
#pragma unroll
            for (int nt = 0; nt < 8; nt++) {
                int d  = nt * 8 + (lane >> 2);
                int kr = ks * 8 + (lane & 3);
                uint32_t b0 = __float_as_uint(Vs[kr][d]);
                uint32_t b1 = __float_as_uint(Vs[kr + 4][d]);
                mma8(o0[nt], aA0, aA1, aA2, aA3, b0, b1);
                mma8(o1[nt], aB0, aB1, aB2, aB3, b0, b1);
            }
        }
    }

    // Epilogue: divide by l, write O for both strips.
    float il0l = 1.f / l_s0l, il0h = 1.f / l_s0h;
    float il1l = 1.f / l_s1l, il1h = 1.f / l_s1h;
    const int or0 = q0 + warp * 32 + (lane >> 2);
#pragma unroll
    for (int nt = 0; nt < 8; nt++) {
        int d = nt * 8 + (lane & 3) * 2;
        *(float2*)&O[base + (size_t)or0        * DIMC + d] =
            make_float2(o0[nt][0] * il0l, o0[nt][1] * il0l);
        *(float2*)&O[base + (size_t)(or0 + 8)  * DIMC + d] =
            make_float2(o0[nt][2] * il0h, o0[nt][3] * il0h);
        *(float2*)&O[base + (size_t)(or0 + 16) * DIMC + d] =
            make_float2(o1[nt][0] * il1l, o1[nt][1] * il1l);
        *(float2*)&O[base + (size_t)(or0 + 24) * DIMC + d] =
            make_float2(o1[nt][2] * il1h, o1[nt][3] * il1h);
    }
}

extern "C" void kernel_launch(void* const* d_in, const int* in_sizes, int n_in,
                              void* d_out, int out_size) {
    (void)in_sizes; (void)n_in; (void)out_size;
    const float* x  = (const float*)d_in[0];
    const float* Wq = (const float*)d_in[1];
    const float* Wk = (const float*)d_in[2];
    const float* Wv = (const float*)d_in[3];
    const float* Wp = (const float*)d_in[4];
    const float* bp = (const float*)d_in[5];
    float* out = (float*)d_out;

    float *qp, *kp, *vp, *op;
    cudaGetSymbolAddress((void**)&qp, g_q);
    cudaGetSymbolAddress((void**)&kp, g_k);
    cudaGetSymbolAddress((void**)&vp, g_v);
    cudaGetSymbolAddress((void**)&op, g_o);

    cudaFuncSetAttribute(attn_kernel, cudaFuncAttributeMaxDynamicSharedMemorySize,
                         ATTN_SMEM);

    dim3 ggrid(DIMC / 128, MROWS / 128);   // (8, 32)
    gemm3x_kernel<<<ggrid, 256>>>(x, Wq, qp, nullptr);
    gemm3x_kernel<<<ggrid, 256>>>(x, Wk, kp, nullptr);
    gemm3x_kernel<<<ggrid, 256>>>(x, Wv, vp, nullptr);
    attn_kernel<<<dim3(SEQ / 128, BATCH * NHEAD), 128, ATTN_SMEM>>>(qp, kp, vp, op);
    gemm3x_kernel<<<ggrid, 256>>>(op, Wp, out, bp);
}

// round 6
// speedup vs baseline: 1.5535x; 1.3894x over previous
#include <cuda_runtime.h>
#include <cstdint>

#define SEQ    2048
#define BATCH  2
#define DIMC   1024
#define NHEAD  16
#define HDIM   64
#define MROWS  (BATCH * SEQ)   // 4096

// Scratch (device globals: no allocation allowed)
__device__ float g_q[MROWS * DIMC];
__device__ float g_k[MROWS * DIMC];
__device__ float g_v[MROWS * DIMC];
__device__ float g_o[MROWS * DIMC];

__device__ __forceinline__ uint32_t tf32r(float x) {
    uint32_t u;
    asm("cvt.rna.tf32.f32 %0, %1;" : "=r"(u) : "f"(x));
    return u;
}

// tf32 m16n8k8 (attention)
__device__ __forceinline__ void mma8(float c[4],
                                     uint32_t a0, uint32_t a1, uint32_t a2, uint32_t a3,
                                     uint32_t b0, uint32_t b1) {
    asm volatile(
        "mma.sync.aligned.m16n8k8.row.col.f32.tf32.tf32.f32 "
        "{%0,%1,%2,%3}, {%4,%5,%6,%7}, {%8,%9}, {%0,%1,%2,%3};"
        : "+f"(c[0]), "+f"(c[1]), "+f"(c[2]), "+f"(c[3])
        : "r"(a0), "r"(a1), "r"(a2), "r"(a3), "r"(b0), "r"(b1));
}

// bf16 m16n8k16 (projection GEMMs)
__device__ __forceinline__ void mma16(float c[4], const uint32_t a[4],
                                      uint32_t b0, uint32_t b1) {
    asm volatile(
        "mma.sync.aligned.m16n8k16.row.col.f32.bf16.bf16.f32 "
        "{%0,%1,%2,%3}, {%4,%5,%6,%7}, {%8,%9}, {%0,%1,%2,%3};"
        : "+f"(c[0]), "+f"(c[1]), "+f"(c[2]), "+f"(c[3])
        : "r"(a[0]), "r"(a[1]), "r"(a[2]), "r"(a[3]), "r"(b0), "r"(b1));
}

// Split float2 (adjacent k values) into packed bf16x2 hi + lo parts.
// low 16 bits = element .x (even k), high 16 bits = element .y (odd k).
__device__ __forceinline__ void bsplit(float2 v, uint32_t& h, uint32_t& l) {
    asm("cvt.rn.bf16x2.f32 %0, %1, %2;" : "=r"(h) : "f"(v.y), "f"(v.x));
    float h0 = __uint_as_float(h << 16);
    float h1 = __uint_as_float(h & 0xffff0000u);
    asm("cvt.rn.bf16x2.f32 %0, %1, %2;" : "=r"(l) : "f"(v.y - h1), "f"(v.x - h0));
}

__device__ __forceinline__ void cp_async16(uint32_t saddr, const void* gaddr) {
    asm volatile("cp.async.ca.shared.global [%0], [%1], 16;" :: "r"(saddr), "l"(gaddr));
}

// ============================================================================
// 3xBF16 GEMM: C[m][n] = sum_k A[m][k] * W[n][k] (+ bias[n])
// Block 128x128, BK=32 (2 x k16 steps), 8 warps (2x4), warp tile 64x32.
// cp.async double-buffered raw fp32 tiles; bf16 hi/lo split at consume.
// Dynamic smem: 2 stages x (A,B) x 128x36 floats = 73728 B.
// ============================================================================
#define GSTAGE (128 * 36)                 // floats per matrix per stage
#define GEMM_SMEM (4 * GSTAGE * 4)        // bytes (2 stages x 2 matrices)

__global__ __launch_bounds__(256, 2)
void gemm3x_kernel(const float* __restrict__ A, const float* __restrict__ W,
                   float* __restrict__ C, const float* __restrict__ bias) {
    extern __shared__ float gsm[];
    // layout: [A stage0][A stage1][B stage0][B stage1]

    const int tid  = threadIdx.x;
    const int lane = tid & 31;
    const int warp = tid >> 5;
    const int wm   = warp >> 2;      // 0..1
    const int wn   = warp & 3;       // 0..3
    const int m0   = blockIdx.y * 128;
    const int n0   = blockIdx.x * 128;

    float acc[4][4][4];
#pragma unroll
    for (int i = 0; i < 4; i++)
#pragma unroll
        for (int j = 0; j < 4; j++)
#pragma unroll
            for (int k = 0; k < 4; k++) acc[i][j][k] = 0.f;

    const int sr2 = tid >> 3;        // 0..31 (staging row within 32-row chunk)
    const int sc2 = (tid & 7) * 4;   // 0..28 (staging col, float4)

    const float* gaA = A + (size_t)(m0 + sr2) * DIMC + sc2;
    const float* gaB = W + (size_t)(n0 + sr2) * DIMC + sc2;

    const uint32_t stageB = GSTAGE * 4;   // bytes per stage
    const uint32_t sA = (uint32_t)__cvta_generic_to_shared(gsm) + (sr2 * 36 + sc2) * 4;
    const uint32_t sB = sA + 2 * stageB;
    const uint32_t rowChunkS = 32 * 36 * 4;      // smem bytes per 32-row chunk
    const size_t   rowChunkG = (size_t)32 * DIMC;

    // Prologue: stage 0
#pragma unroll
    for (int i = 0; i < 4; i++) {
        cp_async16(sA + i * rowChunkS, gaA + i * rowChunkG);
        cp_async16(sB + i * rowChunkS, gaB + i * rowChunkG);
    }
    asm volatile("cp.async.commit_group;");

    const int NT = DIMC / 32;   // 32 iterations
    for (int kt = 0; kt < NT; kt++) {
        const int buf = kt & 1;
        if (kt + 1 < NT) {
            const uint32_t off = (uint32_t)(buf ^ 1) * stageB;
            const int go = (kt + 1) * 32;
#pragma unroll
            for (int i = 0; i < 4; i++) {
                cp_async16(sA + off + i * rowChunkS, gaA + go + i * rowChunkG);
                cp_async16(sB + off + i * rowChunkS, gaB + go + i * rowChunkG);
            }
            asm volatile("cp.async.commit_group;");
            asm volatile("cp.async.wait_group 1;");
        } else {
            asm volatile("cp.async.wait_group 0;");
        }
        __syncthreads();

        const float (*Ab)[36] = (const float(*)[36])(gsm + buf * GSTAGE);
        const float (*Bb)[36] = (const float(*)[36])(gsm + (2 + buf) * GSTAGE);

#pragma unroll
        for (int ks = 0; ks < 2; ks++) {
            const int kk2 = ks * 16 + (lane & 3) * 2;
            uint32_t ah[4][4], al[4][4];
#pragma unroll
            for (int mt = 0; mt < 4; mt++) {
                int r = wm * 64 + mt * 16 + (lane >> 2);
                bsplit(*(const float2*)&Ab[r][kk2],         ah[mt][0], al[mt][0]);
                bsplit(*(const float2*)&Ab[r + 8][kk2],     ah[mt][1], al[mt][1]);
                bsplit(*(const float2*)&Ab[r][kk2 + 8],     ah[mt][2], al[mt][2]);
                bsplit(*(const float2*)&Ab[r + 8][kk2 + 8], ah[mt][3], al[mt][3]);
            }
#pragma unroll
            for (int nt = 0; nt < 4; nt++) {
                int nn = wn * 32 + nt * 8 + (lane >> 2);
                uint32_t bh0, bl0, bh1, bl1;
                bsplit(*(const float2*)&Bb[nn][kk2],     bh0, bl0);
                bsplit(*(const float2*)&Bb[nn][kk2 + 8], bh1, bl1);
#pragma unroll
                for (int mt = 0; mt < 4; mt++) {
                    mma16(acc[mt][nt], ah[mt], bh0, bh1);
                    mma16(acc[mt][nt], al[mt], bh0, bh1);
                    mma16(acc[mt][nt], ah[mt], bl0, bl1);
                }
            }
        }
        __syncthreads();
    }

#pragma unroll
    for (int mt = 0; mt < 4; mt++) {
#pragma unroll
        for (int nt = 0; nt < 4; nt++) {
            int r = m0 + wm * 64 + mt * 16 + (lane >> 2);
            int c = n0 + wn * 32 + nt * 8 + (lane & 3) * 2;
            float bb0 = bias ? bias[c]     : 0.f;
            float bb1 = bias ? bias[c + 1] : 0.f;
            float2 v0 = make_float2(acc[mt][nt][0] + bb0, acc[mt][nt][1] + bb1);
            float2 v1 = make_float2(acc[mt][nt][2] + bb0, acc[mt][nt][3] + bb1);
            *(float2*)&C[(size_t)r       * DIMC + c] = v0;
            *(float2*)&C[(size_t)(r + 8) * DIMC + c] = v1;
        }
    }
}

// ============================================================================
// Flash attention (tf32), 2 Q-strips per warp for B-operand reuse.
// CTA = (b, h, 128 q rows). 4 warps x 32 rows (2 strips of 16).
// Dynamic smem: Ks[64][68] + Vs[64][72] + Ps[128][68] = 70656 B.
// ============================================================================
#define ATTN_SMEM ((64 * 68 + 64 * 72 + 128 * 68) * 4)

__global__ __launch_bounds__(128)
void attn_kernel(const float* __restrict__ Q, const float* __restrict__ K,
                 const float* __restrict__ V, float* __restrict__ O) {
    extern __shared__ float sm[];
    float (*Ks)[68] = (float(*)[68])sm;                       // 64 rows (K tile)
    float (*Vs)[72] = (float(*)[72])(sm + 64 * 68);           // 64 rows (V tile)
    float (*Ps)[68] = (float(*)[68])(sm + 64 * 68 + 64 * 72); // 128 rows (P)

    const int tid  = threadIdx.x;
    const int lane = tid & 31;
    const int warp = tid >> 5;
    const int bh   = blockIdx.y;
    const int b    = bh >> 4;
    const int h    = bh & 15;
    const int q0   = blockIdx.x * 128;
    const size_t base = ((size_t)b * SEQ) * DIMC + (size_t)h * HDIM;

    // Q fragments for both strips, direct from gmem (once), scale folded.
    uint32_t qf[2][8][4];
#pragma unroll
    for (int s = 0; s < 2; s++) {
        int qr = q0 + warp * 32 + s * 16 + (lane >> 2);
        const float* qp0 = Q + base + (size_t)qr * DIMC;
        const float* qp1 = qp0 + (size_t)8 * DIMC;
#pragma unroll
        for (int ks = 0; ks < 8; ks++) {
            int d = ks * 8 + (lane & 3);
            qf[s][ks][0] = tf32r(0.125f * qp0[d]);
            qf[s][ks][1] = tf32r(0.125f * qp1[d]);
            qf[s][ks][2] = tf32r(0.125f * qp0[d + 4]);
            qf[s][ks][3] = tf32r(0.125f * qp1[d + 4]);
        }
    }

    float o0[8][4], o1[8][4];
#pragma unroll
    for (int i = 0; i < 8; i++)
#pragma unroll
        for (int j = 0; j < 4; j++) { o0[i][j] = 0.f; o1[i][j] = 0.f; }
    float m_s0l = -INFINITY, m_s0h = -INFINITY, m_s1l = -INFINITY, m_s1h = -INFINITY;
    float l_s0l = 0.f, l_s0h = 0.f, l_s1l = 0.f, l_s1h = 0.f;

    const int sr = tid >> 4;         // 0..7
    const int sc = (tid & 15) * 4;   // 0..60

    for (int t = 0; t < SEQ / 64; t++) {
        const int k0 = t * 64;
        __syncthreads();
#pragma unroll
        for (int r = sr; r < 64; r += 8) {
            float4 kv = *(const float4*)&K[base + (size_t)(k0 + r) * DIMC + sc];
            float4 vv = *(const float4*)&V[base + (size_t)(k0 + r) * DIMC + sc];
            kv.x = __uint_as_float(tf32r(kv.x)); kv.y = __uint_as_float(tf32r(kv.y));
            kv.z = __uint_as_float(tf32r(kv.z)); kv.w = __uint_as_float(tf32r(kv.w));
            vv.x = __uint_as_float(tf32r(vv.x)); vv.y = __uint_as_float(tf32r(vv.y));
            vv.z = __uint_as_float(tf32r(vv.z)); vv.w = __uint_as_float(tf32r(vv.w));
            *(float4*)&Ks[r][sc] = kv;
            *(float4*)&Vs[r][sc] = vv;
        }
        __syncthreads();

        // S = (0.125*Q) @ K^T for BOTH strips — each K fragment feeds 2 MMAs.
        float s0[8][4], s1[8][4];
#pragma unroll
        for (int i = 0; i < 8; i++)
#pragma unroll
            for (int j = 0; j < 4; j++) { s0[i][j] = 0.f; s1[i][j] = 0.f; }
#pragma unroll
        for (int ks = 0; ks < 8; ks++) {
            const int d = ks * 8 + (lane & 3);
#pragma unroll
            for (int nt = 0; nt < 8; nt++) {
                int key = nt * 8 + (lane >> 2);
                uint32_t b0 = __float_as_uint(Ks[key][d]);
                uint32_t b1 = __float_as_uint(Ks[key][d + 4]);
                mma8(s0[nt], qf[0][ks][0], qf[0][ks][1], qf[0][ks][2], qf[0][ks][3], b0, b1);
                mma8(s1[nt], qf[1][ks][0], qf[1][ks][1], qf[1][ks][2], qf[1][ks][3], b0, b1);
            }
        }

        // Online softmax per strip; write P (tf32) into warp's Ps rows.
        auto softmax_strip = [&](float s[8][4], float& m_lo, float& m_hi,
                                 float& l_lo, float& l_hi, float o[8][4], int prow) {
            float mx_lo = -INFINITY, mx_hi = -INFINITY;
#pragma unroll
            for (int nt = 0; nt < 8; nt++) {
                mx_lo = fmaxf(mx_lo, fmaxf(s[nt][0], s[nt][1]));
                mx_hi = fmaxf(mx_hi, fmaxf(s[nt][2], s[nt][3]));
            }
            mx_lo = fmaxf(mx_lo, __shfl_xor_sync(0xffffffffu, mx_lo, 1));
            mx_lo = fmaxf(mx_lo, __shfl_xor_sync(0xffffffffu, mx_lo, 2));
            mx_hi = fmaxf(mx_hi, __shfl_xor_sync(0xffffffffu, mx_hi, 1));
            mx_hi = fmaxf(mx_hi, __shfl_xor_sync(0xffffffffu, mx_hi, 2));

            float mn_lo = fmaxf(m_lo, mx_lo);
            float mn_hi = fmaxf(m_hi, mx_hi);
            float al_lo = __expf(m_lo - mn_lo);
            float al_hi = __expf(m_hi - mn_hi);
            m_lo = mn_lo; m_hi = mn_hi;

            float sum_lo = 0.f, sum_hi = 0.f;
#pragma unroll
            for (int nt = 0; nt < 8; nt++) {
                s[nt][0] = __expf(s[nt][0] - mn_lo); sum_lo += s[nt][0];
                s[nt][1] = __expf(s[nt][1] - mn_lo); sum_lo += s[nt][1];
                s[nt][2] = __expf(s[nt][2] - mn_hi); sum_hi += s[nt][2];
                s[nt][3] = __expf(s[nt][3] - mn_hi); sum_hi += s[nt][3];
            }
            sum_lo += __shfl_xor_sync(0xffffffffu, sum_lo, 1);
            sum_lo += __shfl_xor_sync(0xffffffffu, sum_lo, 2);
            sum_hi += __shfl_xor_sync(0xffffffffu, sum_hi, 1);
            sum_hi += __shfl_xor_sync(0xffffffffu, sum_hi, 2);
            l_lo = l_lo * al_lo + sum_lo;
            l_hi = l_hi * al_hi + sum_hi;

#pragma unroll
            for (int nt = 0; nt < 8; nt++) {
                o[nt][0] *= al_lo; o[nt][1] *= al_lo;
                o[nt][2] *= al_hi; o[nt][3] *= al_hi;
            }
            const int pr = prow + (lane >> 2);
#pragma unroll
            for (int nt = 0; nt < 8; nt++) {
                int pc = nt * 8 + (lane & 3) * 2;
                float2 p0 = make_float2(__uint_as_float(tf32r(s[nt][0])),
                                        __uint_as_float(tf32r(s[nt][1])));
                float2 p1 = make_float2(__uint_as_float(tf32r(s[nt][2])),
                                        __uint_as_float(tf32r(s[nt][3])));
                *(float2*)&Ps[pr][pc]     = p0;
                *(float2*)&Ps[pr + 8][pc] = p1;
            }
        };

        softmax_strip(s0, m_s0l, m_s0h, l_s0l, l_s0h, o0, warp * 32);
        softmax_strip(s1, m_s1l, m_s1h, l_s1l, l_s1h, o1, warp * 32 + 16);
        __syncwarp();   // Ps writer == reader warp

        // O += P @ V — each V fragment feeds 2 MMAs (both strips).
        const int prA = warp * 32 + (lane >> 2);
#pragma unroll
        for (int ks = 0; ks < 8; ks++) {
            const int pk = ks * 8 + (lane & 3);
            uint32_t aA0 = __float_as_uint(Ps[prA][pk]);
            uint32_t aA1 = __float_as_uint(Ps[prA + 8][pk]);
            uint32_t aA2 = __float_as_uint(Ps[prA][pk + 4]);
            uint32_t aA3 = __float_as_uint(Ps[prA + 8][pk + 4]);
            uint32_t aB0 = __float_as_uint(Ps[prA + 16][pk]);
            uint32_t aB1 = __float_as_uint(Ps[prA + 24][pk]);
            uint32_t aB2 = __float_as_uint(Ps[prA + 16][pk + 4]);
            uint32_t aB3 = __float_as_uint(Ps[prA + 24][pk + 4]);
#pragma unroll
            for (int nt = 0; nt < 8; nt++) {
                int d  = nt * 8 + (lane >> 2);
                int kr = ks * 8 + (lane & 3);
                uint32_t b0 = __float_as_uint(Vs[kr][d]);
                uint32_t b1 = __float_as_uint(Vs[kr + 4][d]);
                mma8(o0[nt], aA0, aA1, aA2, aA3, b0, b1);
                mma8(o1[nt], aB0, aB1, aB2, aB3, b0, b1);
            }
        }
    }

    // Epilogue: divide by l, write O for both strips.
    float il0l = 1.f / l_s0l, il0h = 1.f / l_s0h;
    float il1l = 1.f / l_s1l, il1h = 1.f / l_s1h;
    const int or0 = q0 + warp * 32 + (lane >> 2);
#pragma unroll
    for (int nt = 0; nt < 8; nt++) {
        int d = nt * 8 + (lane & 3) * 2;
        *(float2*)&O[base + (size_t)or0        * DIMC + d] =
            make_float2(o0[nt][0] * il0l, o0[nt][1] * il0l);
        *(float2*)&O[base + (size_t)(or0 + 8)  * DIMC + d] =
            make_float2(o0[nt][2] * il0h, o0[nt][3] * il0h);
        *(float2*)&O[base + (size_t)(or0 + 16) * DIMC + d] =
            make_float2(o1[nt][0] * il1l, o1[nt][1] * il1l);
        *(float2*)&O[base + (size_t)(or0 + 24) * DIMC + d] =
            make_float2(o1[nt][2] * il1h, o1[nt][3] * il1h);
    }
}

extern "C" void kernel_launch(void* const* d_in, const int* in_sizes, int n_in,
                              void* d_out, int out_size) {
    (void)in_sizes; (void)n_in; (void)out_size;
    const float* x  = (const float*)d_in[0];
    const float* Wq = (const float*)d_in[1];
    const float* Wk = (const float*)d_in[2];
    const float* Wv = (const float*)d_in[3];
    const float* Wp = (const float*)d_in[4];
    const float* bp = (const float*)d_in[5];
    float* out = (float*)d_out;

    float *qp, *kp, *vp, *op;
    cudaGetSymbolAddress((void**)&qp, g_q);
    cudaGetSymbolAddress((void**)&kp, g_k);
    cudaGetSymbolAddress((void**)&vp, g_v);
    cudaGetSymbolAddress((void**)&op, g_o);

    cudaFuncSetAttribute(gemm3x_kernel, cudaFuncAttributeMaxDynamicSharedMemorySize,
                         GEMM_SMEM);
    cudaFuncSetAttribute(attn_kernel, cudaFuncAttributeMaxDynamicSharedMemorySize,
                         ATTN_SMEM);

    dim3 ggrid(DIMC / 128, MROWS / 128);   // (8, 32)
    gemm3x_kernel<<<ggrid, 256, GEMM_SMEM>>>(x, Wq, qp, nullptr);
    gemm3x_kernel<<<ggrid, 256, GEMM_SMEM>>>(x, Wk, kp, nullptr);
    gemm3x_kernel<<<ggrid, 256, GEMM_SMEM>>>(x, Wv, vp, nullptr);
    attn_kernel<<<dim3(SEQ / 128, BATCH * NHEAD), 128, ATTN_SMEM>>>(qp, kp, vp, op);
    gemm3x_kernel<<<ggrid, 256, GEMM_SMEM>>>(op, Wp, out, bp);
}

// round 7
// speedup vs baseline: 1.7134x; 1.1029x over previous
#include <cuda_runtime.h>
#include <cstdint>

#define SEQ    2048
#define BATCH  2
#define DIMC   1024
#define NHEAD  16
#define HDIM   64
#define MROWS  (BATCH * SEQ)   // 4096

// Scratch (device globals: no allocation allowed)
__device__ float g_q[MROWS * DIMC];   // holds tf32(0.125 * q)
__device__ float g_k[MROWS * DIMC];   // holds tf32(k)
__device__ float g_v[MROWS * DIMC];   // holds tf32(v)
__device__ float g_o[MROWS * DIMC];

__device__ __forceinline__ uint32_t tf32r(float x) {
    uint32_t u;
    asm("cvt.rna.tf32.f32 %0, %1;" : "=r"(u) : "f"(x));
    return u;
}

// tf32 m16n8k8 (attention)
__device__ __forceinline__ void mma8(float c[4],
                                     uint32_t a0, uint32_t a1, uint32_t a2, uint32_t a3,
                                     uint32_t b0, uint32_t b1) {
    asm volatile(
        "mma.sync.aligned.m16n8k8.row.col.f32.tf32.tf32.f32 "
        "{%0,%1,%2,%3}, {%4,%5,%6,%7}, {%8,%9}, {%0,%1,%2,%3};"
        : "+f"(c[0]), "+f"(c[1]), "+f"(c[2]), "+f"(c[3])
        : "r"(a0), "r"(a1), "r"(a2), "r"(a3), "r"(b0), "r"(b1));
}

// bf16 m16n8k16 (projection GEMMs)
__device__ __forceinline__ void mma16(float c[4], const uint32_t a[4],
                                      uint32_t b0, uint32_t b1) {
    asm volatile(
        "mma.sync.aligned.m16n8k16.row.col.f32.bf16.bf16.f32 "
        "{%0,%1,%2,%3}, {%4,%5,%6,%7}, {%8,%9}, {%0,%1,%2,%3};"
        : "+f"(c[0]), "+f"(c[1]), "+f"(c[2]), "+f"(c[3])
        : "r"(a[0]), "r"(a[1]), "r"(a[2]), "r"(a[3]), "r"(b0), "r"(b1));
}

// Split float2 (adjacent k values) into packed bf16x2 hi + lo parts.
__device__ __forceinline__ void bsplit(float2 v, uint32_t& h, uint32_t& l) {
    asm("cvt.rn.bf16x2.f32 %0, %1, %2;" : "=r"(h) : "f"(v.y), "f"(v.x));
    float h0 = __uint_as_float(h << 16);
    float h1 = __uint_as_float(h & 0xffff0000u);
    asm("cvt.rn.bf16x2.f32 %0, %1, %2;" : "=r"(l) : "f"(v.y - h1), "f"(v.x - h0));
}

__device__ __forceinline__ void cp_async16(uint32_t saddr, const void* gaddr) {
    asm volatile("cp.async.ca.shared.global [%0], [%1], 16;" :: "r"(saddr), "l"(gaddr));
}

// ============================================================================
// 3xBF16 GEMM v3: C[m][n] = sum_k A[m][k] * W[n][k] (+bias / tf32 epilogue)
// Block 256x128, BK=32, 256 threads (8 warps, 4x2), warp tile 64x64.
// 3-stage cp.async ring, prefetch distance 2, ONE barrier per iteration.
// Dynamic smem: 3 stages x (A 256x36 + B 128x36) floats = 165888 B.
// mode: 0 = plain (+bias), 1 = tf32 round, 2 = tf32 round of 0.125*v
// ============================================================================
#define GSTAGE_F (256 * 36 + 128 * 36)      // 13824 floats per stage
#define GEMM_SMEM (3 * GSTAGE_F * 4)

__global__ __launch_bounds__(256, 1)
void gemm3x_kernel(const float* __restrict__ A, const float* __restrict__ W,
                   float* __restrict__ C, const float* __restrict__ bias,
                   int mode) {
    extern __shared__ float gsm[];

    const int tid  = threadIdx.x;
    const int lane = tid & 31;
    const int warp = tid >> 5;
    const int wm   = warp >> 1;      // 0..3
    const int wn   = warp & 1;       // 0..1
    const int m0   = blockIdx.y * 256;
    const int n0   = blockIdx.x * 128;

    float acc[4][8][4];
#pragma unroll
    for (int i = 0; i < 4; i++)
#pragma unroll
        for (int j = 0; j < 8; j++)
#pragma unroll
            for (int k = 0; k < 4; k++) acc[i][j][k] = 0.f;

    const int sr = tid >> 3;         // 0..31 (staging row within 32-row chunk)
    const int sc = (tid & 7) * 4;    // 0..28 (staging col, float4)

    const float* gaA = A + (size_t)(m0 + sr) * DIMC + sc;
    const float* gaB = W + (size_t)(n0 + sr) * DIMC + sc;

    const uint32_t smBase = (uint32_t)__cvta_generic_to_shared(gsm);
    const uint32_t sA = smBase + (uint32_t)(sr * 36 + sc) * 4u;
    const uint32_t sB = smBase + (uint32_t)(256 * 36 + sr * 36 + sc) * 4u;
    const uint32_t rowChunkS = 32 * 36 * 4;     // smem bytes per 32-row chunk
    const size_t   rowChunkG = (size_t)32 * DIMC;
    const uint32_t stageB = GSTAGE_F * 4;

    auto prefetch = [&](int tile, int stage) {
        const uint32_t so = (uint32_t)stage * stageB;
        const int go = tile * 32;
#pragma unroll
        for (int i = 0; i < 8; i++)
            cp_async16(sA + so + i * rowChunkS, gaA + go + i * rowChunkG);
#pragma unroll
        for (int i = 0; i < 4; i++)
            cp_async16(sB + so + i * rowChunkS, gaB + go + i * rowChunkG);
        asm volatile("cp.async.commit_group;");
    };

    const int NT = DIMC / 32;   // 32
    prefetch(0, 0);
    prefetch(1, 1);

    int stage = 0;
    for (int kt = 0; kt < NT; kt++) {
        if (kt + 1 < NT) asm volatile("cp.async.wait_group 1;");
        else             asm volatile("cp.async.wait_group 0;");
        __syncthreads();

        const float (*Ab)[36] = (const float(*)[36])(gsm + stage * GSTAGE_F);
        const float (*Bb)[36] = (const float(*)[36])(gsm + stage * GSTAGE_F + 256 * 36);

#pragma unroll
        for (int ks = 0; ks < 2; ks++) {
            const int kk2 = ks * 16 + (lane & 3) * 2;
            uint32_t ah[4][4], al[4][4];
#pragma unroll
            for (int mt = 0; mt < 4; mt++) {
                int r = wm * 64 + mt * 16 + (lane >> 2);
                bsplit(*(const float2*)&Ab[r][kk2],         ah[mt][0], al[mt][0]);
                bsplit(*(const float2*)&Ab[r + 8][kk2],     ah[mt][1], al[mt][1]);
                bsplit(*(const float2*)&Ab[r][kk2 + 8],     ah[mt][2], al[mt][2]);
                bsplit(*(const float2*)&Ab[r + 8][kk2 + 8], ah[mt][3], al[mt][3]);
            }
#pragma unroll
            for (int nt = 0; nt < 8; nt++) {
                int nn = wn * 64 + nt * 8 + (lane >> 2);
                uint32_t bh0, bl0, bh1, bl1;
                bsplit(*(const float2*)&Bb[nn][kk2],     bh0, bl0);
                bsplit(*(const float2*)&Bb[nn][kk2 + 8], bh1, bl1);
#pragma unroll
                for (int mt = 0; mt < 4; mt++) {
                    mma16(acc[mt][nt], ah[mt], bh0, bh1);
                    mma16(acc[mt][nt], al[mt], bh0, bh1);
                    mma16(acc[mt][nt], ah[mt], bl0, bl1);
                }
            }
        }

        if (kt + 2 < NT) {
            int ns = stage + 2; if (ns >= 3) ns -= 3;
            prefetch(kt + 2, ns);
        }
        stage++; if (stage == 3) stage = 0;
    }

#pragma unroll
    for (int mt = 0; mt < 4; mt++) {
#pragma unroll
        for (int nt = 0; nt < 8; nt++) {
            int r = m0 + wm * 64 + mt * 16 + (lane >> 2);
            int c = n0 + wn * 64 + nt * 8 + (lane & 3) * 2;
            float v0 = acc[mt][nt][0], v1 = acc[mt][nt][1];
            float v2 = acc[mt][nt][2], v3 = acc[mt][nt][3];
            if (mode == 0) {
                if (bias) {
                    float bb0 = bias[c], bb1 = bias[c + 1];
                    v0 += bb0; v1 += bb1; v2 += bb0; v3 += bb1;
                }
            } else if (mode == 1) {
                v0 = __uint_as_float(tf32r(v0)); v1 = __uint_as_float(tf32r(v1));
                v2 = __uint_as_float(tf32r(v2)); v3 = __uint_as_float(tf32r(v3));
            } else {
                v0 = __uint_as_float(tf32r(0.125f * v0));
                v1 = __uint_as_float(tf32r(0.125f * v1));
                v2 = __uint_as_float(tf32r(0.125f * v2));
                v3 = __uint_as_float(tf32r(0.125f * v3));
            }
            *(float2*)&C[(size_t)r       * DIMC + c] = make_float2(v0, v1);
            *(float2*)&C[(size_t)(r + 8) * DIMC + c] = make_float2(v2, v3);
        }
    }
}

// ============================================================================
// Flash attention (tf32), 2 Q-strips per warp, cp.async double-buffered K/V.
// CTA = (b, h, 128 q rows). 4 warps x 32 rows. K/V/Q arrive pre-tf32-rounded.
// Dynamic smem: 2 x (Ks 64x68 + Vs 64x72) + Ps 128x68 = 106496 B.
// ============================================================================
#define ATTN_STAGE_F (64 * 68 + 64 * 72)   // 8960 floats per stage
#define ATTN_SMEM ((2 * ATTN_STAGE_F + 128 * 68) * 4)

__global__ __launch_bounds__(128)
void attn_kernel(const float* __restrict__ Q, const float* __restrict__ K,
                 const float* __restrict__ V, float* __restrict__ O) {
    extern __shared__ float sm[];
    float (*Ps)[68] = (float(*)[68])(sm + 2 * ATTN_STAGE_F);

    const int tid  = threadIdx.x;
    const int lane = tid & 31;
    const int warp = tid >> 5;
    const int bh   = blockIdx.y;
    const int b    = bh >> 4;
    const int h    = bh & 15;
    const int q0   = blockIdx.x * 128;
    const size_t base = ((size_t)b * SEQ) * DIMC + (size_t)h * HDIM;

    const int sr = tid >> 4;         // 0..7
    const int sc = (tid & 15) * 4;   // 0..60

    const uint32_t smBase = (uint32_t)__cvta_generic_to_shared(sm);

    auto prefetchKV = [&](int t, int s) {
        const int k0 = t * 64;
        const uint32_t so = (uint32_t)s * (ATTN_STAGE_F * 4u);
#pragma unroll
        for (int rr = 0; rr < 8; rr++) {
            int r = sr + rr * 8;
            cp_async16(smBase + so + (uint32_t)(r * 68 + sc) * 4u,
                       &K[base + (size_t)(k0 + r) * DIMC + sc]);
            cp_async16(smBase + so + (uint32_t)(64 * 68 + r * 72 + sc) * 4u,
                       &V[base + (size_t)(k0 + r) * DIMC + sc]);
        }
        asm volatile("cp.async.commit_group;");
    };

    // Kick off tile 0 before the (long-scoreboard) Q fragment loads.
    prefetchKV(0, 0);

    // Q fragments for both strips; Q already holds tf32(0.125*q).
    uint32_t qf[2][8][4];
#pragma unroll
    for (int s = 0; s < 2; s++) {
        int qr = q0 + warp * 32 + s * 16 + (lane >> 2);
        const float* qp0 = Q + base + (size_t)qr * DIMC;
        const float* qp1 = qp0 + (size_t)8 * DIMC;
#pragma unroll
        for (int ks = 0; ks < 8; ks++) {
            int d = ks * 8 + (lane & 3);
            qf[s][ks][0] = __float_as_uint(qp0[d]);
            qf[s][ks][1] = __float_as_uint(qp1[d]);
            qf[s][ks][2] = __float_as_uint(qp0[d + 4]);
            qf[s][ks][3] = __float_as_uint(qp1[d + 4]);
        }
    }

    float o0[8][4], o1[8][4];
#pragma unroll
    for (int i = 0; i < 8; i++)
#pragma unroll
        for (int j = 0; j < 4; j++) { o0[i][j] = 0.f; o1[i][j] = 0.f; }
    float m_s0l = -INFINITY, m_s0h = -INFINITY, m_s1l = -INFINITY, m_s1h = -INFINITY;
    float l_s0l = 0.f, l_s0h = 0.f, l_s1l = 0.f, l_s1h = 0.f;

    for (int t = 0; t < SEQ / 64; t++) {
        const int buf = t & 1;
        __syncthreads();   // all warps done reading stage buf^1 (iter t-1)
        if (t + 1 < SEQ / 64) {
            prefetchKV(t + 1, buf ^ 1);
            asm volatile("cp.async.wait_group 1;");
        } else {
            asm volatile("cp.async.wait_group 0;");
        }
        __syncthreads();   // stage buf visible to all warps

        const float (*Ks)[68] = (const float(*)[68])(sm + buf * ATTN_STAGE_F);
        const float (*Vs)[72] = (const float(*)[72])(sm + buf * ATTN_STAGE_F + 64 * 68);

        // S = Qs @ K^T for BOTH strips — each K fragment feeds 2 MMAs.
        float s0[8][4], s1[8][4];
#pragma unroll
        for (int i = 0; i < 8; i++)
#pragma unroll
            for (int j = 0; j < 4; j++) { s0[i][j] = 0.f; s1[i][j] = 0.f; }
#pragma unroll
        for (int ks = 0; ks < 8; ks++) {
            const int d = ks * 8 + (lane & 3);
#pragma unroll
            for (int nt = 0; nt < 8; nt++) {
                int key = nt * 8 + (lane >> 2);
                uint32_t b0 = __float_as_uint(Ks[key][d]);
                uint32_t b1 = __float_as_uint(Ks[key][d + 4]);
                mma8(s0[nt], qf[0][ks][0], qf[0][ks][1], qf[0][ks][2], qf[0][ks][3], b0, b1);
                mma8(s1[nt], qf[1][ks][0], qf[1][ks][1], qf[1][ks][2], qf[1][ks][3], b0, b1);
            }
        }

        // Online softmax per strip; write P (tf32) into warp's Ps rows.
        auto softmax_strip = [&](float s[8][4], float& m_lo, float& m_hi,
                                 float& l_lo, float& l_hi, float o[8][4], int prow) {
            float mx_lo = -INFINITY, mx_hi = -INFINITY;
#pragma unroll
            for (int nt = 0; nt < 8; nt++) {
                mx_lo = fmaxf(mx_lo, fmaxf(s[nt][0], s[nt][1]));
                mx_hi = fmaxf(mx_hi, fmaxf(s[nt][2], s[nt][3]));
            }
            mx_lo = fmaxf(mx_lo, __shfl_xor_sync(0xffffffffu, mx_lo, 1));
            mx_lo = fmaxf(mx_lo, __shfl_xor_sync(0xffffffffu, mx_lo, 2));
            mx_hi = fmaxf(mx_hi, __shfl_xor_sync(0xffffffffu, mx_hi, 1));
            mx_hi = fmaxf(mx_hi, __shfl_xor_sync(0xffffffffu, mx_hi, 2));

            float mn_lo = fmaxf(m_lo, mx_lo);
            float mn_hi = fmaxf(m_hi, mx_hi);
            float al_lo = __expf(m_lo - mn_lo);
            float al_hi = __expf(m_hi - mn_hi);
            m_lo = mn_lo; m_hi = mn_hi;

            float sum_lo = 0.f, sum_hi = 0.f;
#pragma unroll
            for (int nt = 0; nt < 8; nt++) {
                s[nt][0] = __expf(s[nt][0] - mn_lo); sum_lo += s[nt][0];
                s[nt][1] = __expf(s[nt][1] - mn_lo); sum_lo += s[nt][1];
                s[nt][2] = __expf(s[nt][2] - mn_hi); sum_hi += s[nt][2];
                s[nt][3] = __expf(s[nt][3] - mn_hi); sum_hi += s[nt][3];
            }
            sum_lo += __shfl_xor_sync(0xffffffffu, sum_lo, 1);
            sum_lo += __shfl_xor_sync(0xffffffffu, sum_lo, 2);
            sum_hi += __shfl_xor_sync(0xffffffffu, sum_hi, 1);
            sum_hi += __shfl_xor_sync(0xffffffffu, sum_hi, 2);
            l_lo = l_lo * al_lo + sum_lo;
            l_hi = l_hi * al_hi + sum_hi;

#pragma unroll
            for (int nt = 0; nt < 8; nt++) {
                o[nt][0] *= al_lo; o[nt][1] *= al_lo;
                o[nt][2] *= al_hi; o[nt][3] *= al_hi;
            }
            const int pr = prow + (lane >> 2);
#pragma unroll
            for (int nt = 0; nt < 8; nt++) {
                int pc = nt * 8 + (lane & 3) * 2;
                float2 p0 = make_float2(__uint_as_float(tf32r(s[nt][0])),
                                        __uint_as_float(tf32r(s[nt][1])));
                float2 p1 = make_float2(__uint_as_float(tf32r(s[nt][2])),
                                        __uint_as_float(tf32r(s[nt][3])));
                *(float2*)&Ps[pr][pc]     = p0;
                *(float2*)&Ps[pr + 8][pc] = p1;
            }
        };

        softmax_strip(s0, m_s0l, m_s0h, l_s0l, l_s0h, o0, warp * 32);
        softmax_strip(s1, m_s1l, m_s1h, l_s1l, l_s1h, o1, warp * 32 + 16);
        __syncwarp();   // Ps writer == reader warp

        // O += P @ V — each V fragment feeds 2 MMAs (both strips).
        const int prA = warp * 32 + (lane >> 2);
#pragma unroll
        for (int ks = 0; ks < 8; ks++) {
            const int pk = ks * 8 + (lane & 3);
            uint32_t aA0 = __float_as_uint(Ps[prA][pk]);
            uint32_t aA1 = __float_as_uint(Ps[prA + 8][pk]);
            uint32_t aA2 = __float_as_uint(Ps[prA][pk + 4]);
            uint32_t aA3 = __float_as_uint(Ps[prA + 8][pk + 4]);
            uint32_t aB0 = __float_as_uint(Ps[prA + 16][pk]);
            uint32_t aB1 = __float_as_uint(Ps[prA + 24][pk]);
            uint32_t aB2 = __float_as_uint(Ps[prA + 16][pk + 4]);
            uint32_t aB3 = __float_as_uint(Ps[prA + 24][pk + 4]);
#pragma unroll
            for (int nt = 0; nt < 8; nt++) {
                int d  = nt * 8 + (lane >> 2);
                int kr = ks * 8 + (lane & 3);
                uint32_t b0 = __float_as_uint(Vs[kr][d]);
                uint32_t b1 = __float_as_uint(Vs[kr + 4][d]);
                mma8(o0[nt], aA0, aA1, aA2, aA3, b0, b1);
                mma8(o1[nt], aB0, aB1, aB2, aB3, b0, b1);
            }
        }
    }

    // Epilogue: divide by l, write O for both strips.
    float il0l = 1.f / l_s0l, il0h = 1.f / l_s0h;
    float il1l = 1.f / l_s1l, il1h = 1.f / l_s1h;
    const int or0 = q0 + warp * 32 + (lane >> 2);
#pragma unroll
    for (int nt = 0; nt < 8; nt++) {
        int d = nt * 8 + (lane & 3) * 2;
        *(float2*)&O[base + (size_t)or0        * DIMC + d] =
            make_float2(o0[nt][0] * il0l, o0[nt][1] * il0l);
        *(float2*)&O[base + (size_t)(or0 + 8)  * DIMC + d] =
            make_float2(o0[nt][2] * il0h, o0[nt][3] * il0h);
        *(float2*)&O[base + (size_t)(or0 + 16) * DIMC + d] =
            make_float2(o1[nt][0] * il1l, o1[nt][1] * il1l);
        *(float2*)&O[base + (size_t)(or0 + 24) * DIMC + d] =
            make_float2(o1[nt][2] * il1h, o1[nt][3] * il1h);
    }
}

extern "C" void kernel_launch(void* const* d_in, const int* in_sizes, int n_in,
                              void* d_out, int out_size) {
    (void)in_sizes; (void)n_in; (void)out_size;
    const float* x  = (const float*)d_in[0];
    const float* Wq = (const float*)d_in[1];
    const float* Wk = (const float*)d_in[2];
    const float* Wv = (const float*)d_in[3];
    const float* Wp = (const float*)d_in[4];
    const float* bp = (const float*)d_in[5];
    float* out = (float*)d_out;

    float *qp, *kp, *vp, *op;
    cudaGetSymbolAddress((void**)&qp, g_q);
    cudaGetSymbolAddress((void**)&kp, g_k);
    cudaGetSymbolAddress((void**)&vp, g_v);
    cudaGetSymbolAddress((void**)&op, g_o);

    cudaFuncSetAttribute(gemm3x_kernel, cudaFuncAttributeMaxDynamicSharedMemorySize,
                         GEMM_SMEM);
    cudaFuncSetAttribute(attn_kernel, cudaFuncAttributeMaxDynamicSharedMemorySize,
                         ATTN_SMEM);

    dim3 ggrid(DIMC / 128, MROWS / 256);   // (8, 16)
    gemm3x_kernel<<<ggrid, 256, GEMM_SMEM>>>(x, Wq, qp, nullptr, 2);
    gemm3x_kernel<<<ggrid, 256, GEMM_SMEM>>>(x, Wk, kp, nullptr, 1);
    gemm3x_kernel<<<ggrid, 256, GEMM_SMEM>>>(x, Wv, vp, nullptr, 1);
    attn_kernel<<<dim3(SEQ / 128, BATCH * NHEAD), 128, ATTN_SMEM>>>(qp, kp, vp, op);
    gemm3x_kernel<<<ggrid, 256, GEMM_SMEM>>>(op, Wp, out, bp, 0);
}